// round 5
// baseline (speedup 1.0000x reference)
#include <cuda_runtime.h>
#include <math.h>

#define NB 128
#define NJ 32
#define NI 1152
#define NN 16
#define TI 32
#define NTILES 36
#define DSTR 33

// ---------- global scratch ----------
__device__ float    g_V0[NB * NJ * NN];
__device__ float    g_V1[NB * NJ * NN];
__device__ float    g_VW[NB * NJ * NN];                // v0 + v1
__device__ float    g_S_part[NTILES * NB * NJ * NN];
__device__ float    g_sc_part[NTILES * NB * NJ];
__device__ float    g_ent_part[2 * NTILES * NB];
__device__ unsigned g_mask1[NB];
__device__ unsigned g_mask2[NB];

__device__ __forceinline__ float wsum32(float v) {
#pragma unroll
    for (int o = 16; o; o >>= 1) v += __shfl_xor_sync(0xFFFFFFFFu, v, o);
    return v;
}
__device__ __forceinline__ float wmax32(float v) {
#pragma unroll
    for (int o = 16; o; o >>= 1) v = fmaxf(v, __shfl_xor_sync(0xFFFFFFFFu, v, o));
    return v;
}

// =====================================================================
// Pass 1: s0 = (1/32)*sum_i u ; v0 = squash(s0 + bias)
// =====================================================================
__global__ void __launch_bounds__(256) pass1_kernel(const float* __restrict__ u,
                                                    const float* __restrict__ bias) {
    __shared__ float sred[64 * 17];
    int j = blockIdx.x, b = blockIdx.y;
    int t = threadIdx.x;
    int q = t & 3, ir = t >> 2;
    const float* base = u + (size_t)(b * NJ + j) * (NI * NN);
    float4 acc = make_float4(0.f, 0.f, 0.f, 0.f);
#pragma unroll
    for (int k = 0; k < 18; ++k) {
        int i = ir + k * 64;
        float4 v = *reinterpret_cast<const float4*>(base + (size_t)i * NN + q * 4);
        acc.x += v.x; acc.y += v.y; acc.z += v.z; acc.w += v.w;
    }
    float* sp = sred + ir * 17 + q * 4;
    sp[0] = acc.x; sp[1] = acc.y; sp[2] = acc.z; sp[3] = acc.w;
    __syncthreads();
    if (t < 16) {
        int n = t;
        float s = 0.f;
        for (int r = 0; r < 64; ++r) s += sred[r * 17 + n];
        s *= (1.f / 32.f);
        float ss = s;
#pragma unroll
        for (int o = 8; o; o >>= 1) ss += __shfl_xor_sync(0xFFFFu, ss, o);
        float tb = (ss == 0.f) ? 0.f : (s + bias[j * NN + n]);
        float sq = tb * tb;
#pragma unroll
        for (int o = 8; o; o >>= 1) sq += __shfl_xor_sync(0xFFFFu, sq, o);
        float v = (sq / (1.f + sq)) * tb / sqrtf(sq + 1e-8f);
        g_V0[(b * NJ + j) * NN + n] = v;
    }
}

// =====================================================================
// SCORE sweep over selected j: batched register dots -> masked softmax
// -> node-score partials.
// =====================================================================
template <int KSEL>
__global__ void __launch_bounds__(256) score_kernel(const float* __restrict__ u,
                                                    const float* __restrict__ vglob,
                                                    const unsigned* __restrict__ maskp) {
    constexpr int SLOTS = (KSEL + 7) / 8;
    __shared__ float sd[32 * DSTR];
    __shared__ int   sj[32];
    int t = threadIdx.x, lane = t & 31, w = t >> 5;
    int tb = blockIdx.x, b = blockIdx.y, i0 = tb * TI;
    int q = lane & 3, ig = lane >> 2;
    unsigned msk = maskp ? maskp[b] : 0xFFFFFFFFu;
    if (t < 32 && ((msk >> t) & 1u))
        sj[__popc(msk & ((1u << t) - 1u))] = t;
    __syncthreads();

    const float* ub = u + (size_t)b * (NJ * NI * NN);
    bool act[SLOTS]; int jl[SLOTS]; float4 vj[SLOTS];
    const float* bp[SLOTS];
#pragma unroll
    for (int sl = 0; sl < SLOTS; ++sl) {
        act[sl] = (sl * 8 + w) < KSEL;
        jl[sl]  = act[sl] ? sj[sl * 8 + w] : 0;
        vj[sl]  = *reinterpret_cast<const float4*>(vglob + (b * NJ + jl[sl]) * NN + q * 4);
        bp[sl]  = ub + (size_t)jl[sl] * (NI * NN) + (size_t)(i0 + ig) * NN + q * 4;
    }

#pragma unroll
    for (int m = 0; m < 4; ++m) {
        float4 r[SLOTS];
#pragma unroll
        for (int sl = 0; sl < SLOTS; ++sl)
            if (act[sl]) r[sl] = *reinterpret_cast<const float4*>(bp[sl] + m * 8 * NN);
#pragma unroll
        for (int sl = 0; sl < SLOTS; ++sl) if (act[sl]) {
            float d = r[sl].x * vj[sl].x + r[sl].y * vj[sl].y + r[sl].z * vj[sl].z + r[sl].w * vj[sl].w;
            d += __shfl_xor_sync(0xFFFFFFFFu, d, 1);
            d += __shfl_xor_sync(0xFFFFFFFFu, d, 2);
            if (q == 0) sd[(m * 8 + ig) * DSTR + jl[sl]] = d;
        }
    }
    __syncthreads();
#pragma unroll
    for (int s = 0; s < 4; ++s) {
        int il = w * 4 + s;
        float d = sd[il * DSTR + lane];
        bool sel = (msk >> lane) & 1u;
        float mx = wmax32(sel ? d : -INFINITY);
        float e = sel ? expf(d - mx) : 0.f;
        float S = wsum32(e);
        sd[il * DSTR + lane] = e / S;
    }
    __syncthreads();
#pragma unroll
    for (int p = 0; p < 4; ++p) {
        int j = w * 4 + p;
        bool selj = (msk >> j) & 1u;
        float c = wsum32(selj ? sd[lane * DSTR + j] : 0.f);
        if (lane == 0) g_sc_part[tb * (NB * NJ) + b * NJ + j] = c;
    }
}

// =====================================================================
// SUM sweep: phase A dots (streams u, populates L1), balanced softmax
// + entropy, phase B re-reads u from L1 for s accumulation.
// =====================================================================
template <int KSEL>
__global__ void __launch_bounds__(256, 4) sum_kernel(const float* __restrict__ u,
                                                     const float* __restrict__ vglob,
                                                     const unsigned* __restrict__ maskp,
                                                     int ent_slot) {
    constexpr int SLOTS = (KSEL + 7) / 8;
    __shared__ float sd[32 * DSTR];
    __shared__ int   sj[32];
    __shared__ float red[8];
    int t = threadIdx.x, lane = t & 31, w = t >> 5;
    int tb = blockIdx.x, b = blockIdx.y, i0 = tb * TI;
    int q = lane & 3, ig = lane >> 2;
    unsigned msk = maskp[b];
    if (t < 32 && ((msk >> t) & 1u))
        sj[__popc(msk & ((1u << t) - 1u))] = t;
    __syncthreads();

    const float* ub = u + (size_t)b * (NJ * NI * NN);
    bool act[SLOTS]; int jl[SLOTS]; float4 vj[SLOTS];
    const float* bp[SLOTS];
#pragma unroll
    for (int sl = 0; sl < SLOTS; ++sl) {
        act[sl] = (sl * 8 + w) < KSEL;
        jl[sl]  = act[sl] ? sj[sl * 8 + w] : 0;
        vj[sl]  = *reinterpret_cast<const float4*>(vglob + (b * NJ + jl[sl]) * NN + q * 4);
        bp[sl]  = ub + (size_t)jl[sl] * (NI * NN) + (size_t)(i0 + ig) * NN + q * 4;
    }

    // phase A: dots
#pragma unroll
    for (int m = 0; m < 4; ++m) {
        float4 r[SLOTS];
#pragma unroll
        for (int sl = 0; sl < SLOTS; ++sl)
            if (act[sl]) r[sl] = *reinterpret_cast<const float4*>(bp[sl] + m * 8 * NN);
#pragma unroll
        for (int sl = 0; sl < SLOTS; ++sl) if (act[sl]) {
            float d = r[sl].x * vj[sl].x + r[sl].y * vj[sl].y + r[sl].z * vj[sl].z + r[sl].w * vj[sl].w;
            d += __shfl_xor_sync(0xFFFFFFFFu, d, 1);
            d += __shfl_xor_sync(0xFFFFFFFFu, d, 2);
            if (q == 0) sd[(m * 8 + ig) * DSTR + jl[sl]] = d;
        }
    }
    __syncthreads();

    // softmax + entropy (4 rows per warp, balanced)
    float ent_acc = 0.f;
#pragma unroll
    for (int s = 0; s < 4; ++s) {
        int il = w * 4 + s;
        float d = sd[il * DSTR + lane];
        bool sel = (msk >> lane) & 1u;
        float mx = wmax32(sel ? d : -INFINITY);
        float e = sel ? expf(d - mx) : 0.f;
        float S = wsum32(e);
        float c = e / S;
        sd[il * DSTR + lane] = c;
        float cds = wsum32(sel ? c * d : 0.f);
        ent_acc += (mx + logf(S) - cds);
    }
    __syncthreads();

    // phase B: re-read u (L1-resident) and accumulate s
    float4 acc[SLOTS];
#pragma unroll
    for (int sl = 0; sl < SLOTS; ++sl) acc[sl] = make_float4(0.f, 0.f, 0.f, 0.f);
#pragma unroll
    for (int m = 0; m < 4; ++m) {
        float4 r[SLOTS];
#pragma unroll
        for (int sl = 0; sl < SLOTS; ++sl)
            if (act[sl]) r[sl] = *reinterpret_cast<const float4*>(bp[sl] + m * 8 * NN);
#pragma unroll
        for (int sl = 0; sl < SLOTS; ++sl) if (act[sl]) {
            float c = sd[(m * 8 + ig) * DSTR + jl[sl]];
            acc[sl].x += c * r[sl].x;
            acc[sl].y += c * r[sl].y;
            acc[sl].z += c * r[sl].z;
            acc[sl].w += c * r[sl].w;
        }
    }
#pragma unroll
    for (int sl = 0; sl < SLOTS; ++sl) {
#pragma unroll
        for (int o = 4; o < 32; o <<= 1) {
            acc[sl].x += __shfl_xor_sync(0xFFFFFFFFu, acc[sl].x, o);
            acc[sl].y += __shfl_xor_sync(0xFFFFFFFFu, acc[sl].y, o);
            acc[sl].z += __shfl_xor_sync(0xFFFFFFFFu, acc[sl].z, o);
            acc[sl].w += __shfl_xor_sync(0xFFFFFFFFu, acc[sl].w, o);
        }
        if (ig == 0 && act[sl]) {
            size_t so = (size_t)tb * (NB * NJ * NN) + (size_t)(b * NJ + jl[sl]) * NN + q * 4;
            *reinterpret_cast<float4*>(g_S_part + so) = acc[sl];
        }
    }
    if (lane == 0) red[w] = ent_acc;
    __syncthreads();
    if (t == 0) {
        float e = 0.f;
#pragma unroll
        for (int x = 0; x < 8; ++x) e += red[x];
        g_ent_part[ent_slot * (NTILES * NB) + tb * NB + b] = e;
    }
}

// =====================================================================
// top-k per example (tie-break: lower index wins)
// =====================================================================
__global__ void topk_kernel(int K, int which) {
    int b = blockIdx.x, j = threadIdx.x;
    float sc = 0.f;
#pragma unroll 6
    for (int tt = 0; tt < NTILES; ++tt) sc += g_sc_part[tt * (NB * NJ) + b * NJ + j];
    int rank = 0;
#pragma unroll
    for (int k = 0; k < 32; ++k) {
        float o = __shfl_sync(0xFFFFFFFFu, sc, k);
        rank += (o > sc) || (o == sc && k < j);
    }
    unsigned m = __ballot_sync(0xFFFFFFFFu, rank < K);
    if (j == 0) {
        if (which == 1) g_mask1[b] = m; else g_mask2[b] = m;
    }
}

// =====================================================================
// squash from s partials (mask-aware; unselected capsules -> v = 0)
// =====================================================================
__device__ __forceinline__ float squash_elem(int gid, bool sel, const float* __restrict__ bias) {
    float s = 0.f;
    if (sel) {
#pragma unroll 6
        for (int tt = 0; tt < NTILES; ++tt) s += g_S_part[(size_t)tt * (NB * NJ * NN) + gid];
    }
    float ss = s;
#pragma unroll
    for (int o = 8; o; o >>= 1) ss += __shfl_xor_sync(0xFFFFFFFFu, ss, o);
    int n = gid & 15, j = (gid >> 4) & 31;
    float tb = (ss == 0.f) ? 0.f : (s + bias[j * NN + n]);
    float sq = tb * tb;
#pragma unroll
    for (int o = 8; o; o >>= 1) sq += __shfl_xor_sync(0xFFFFFFFFu, sq, o);
    return (sq == 0.f) ? 0.f : (sq / (1.f + sq)) * tb / sqrtf(sq + 1e-8f);
}

__global__ void __launch_bounds__(256) squash_mid_kernel(const float* __restrict__ bias) {
    int gid = blockIdx.x * 256 + threadIdx.x;
    int j = (gid >> 4) & 31, b = gid >> 9;
    bool sel = (g_mask1[b] >> j) & 1u;
    float v = squash_elem(gid, sel, bias);
    g_V1[gid] = v;
    g_VW[gid] = g_V0[gid] + v;
}

__global__ void __launch_bounds__(256) final_kernel(const float* __restrict__ bias,
                                                    float* __restrict__ out, int out_size) {
    int gid = blockIdx.x * 256 + threadIdx.x;
    int j = (gid >> 4) & 31, b = gid >> 9;
    bool sel = (g_mask2[b] >> j) & 1u;
    out[gid] = squash_elem(gid, sel, bias);
    if (blockIdx.x == 0 && threadIdx.x < NB && out_size >= NB * NJ * NN + NB * 3) {
        int bb = threadIdx.x;
        float e1 = 0.f, e2 = 0.f;
        for (int tt = 0; tt < NTILES; ++tt) {
            e1 += g_ent_part[0 * (NTILES * NB) + tt * NB + bb];
            e2 += g_ent_part[1 * (NTILES * NB) + tt * NB + bb];
        }
        float* eo = out + NB * NJ * NN;
        eo[bb * 3 + 0] = logf(32.0f);
        eo[bb * 3 + 1] = e1 * (1.f / (float)NI);
        eo[bb * 3 + 2] = e2 * (1.f / (float)NI);
    }
}

// =====================================================================
extern "C" void kernel_launch(void* const* d_in, const int* in_sizes, int n_in,
                              void* d_out, int out_size) {
    const float* u    = (const float*)d_in[0];
    const float* bias = (const float*)d_in[1];
    float* out        = (float*)d_out;

    float *v0p, *vwp;
    unsigned *m1p, *m2p;
    cudaGetSymbolAddress((void**)&v0p, g_V0);
    cudaGetSymbolAddress((void**)&vwp, g_VW);
    cudaGetSymbolAddress((void**)&m1p, g_mask1);
    cudaGetSymbolAddress((void**)&m2p, g_mask2);

    dim3 sgrid(NTILES, NB);

    // sweep 1 (302 MB): s0 -> v0
    pass1_kernel<<<dim3(NJ, NB), 256>>>(u, bias);
    // sweep 2 (302 MB): scores of softmax(u·v0) -> top-20 -> mask1
    score_kernel<32><<<sgrid, 256>>>(u, v0p, nullptr);
    topk_kernel<<<NB, 32>>>(20, 1);
    // sweep 3 (189 MB): c1, entropy1, s1 -> v1, w = v0 + v1
    sum_kernel<20><<<sgrid, 256>>>(u, v0p, m1p, 0);
    squash_mid_kernel<<<256, 256>>>(bias);
    // sweep 4 (189 MB): scores of softmax(u·w, mask1) -> top-12 -> mask2
    score_kernel<20><<<sgrid, 256>>>(u, vwp, m1p);
    topk_kernel<<<NB, 32>>>(12, 2);
    // sweep 5 (113 MB): c2, entropy2, s2 -> v2 (out)
    sum_kernel<12><<<sgrid, 256>>>(u, vwp, m2p, 1);
    final_kernel<<<256, 256>>>(bias, out, out_size);
}

// round 7
// speedup vs baseline: 1.1732x; 1.1732x over previous
#include <cuda_runtime.h>
#include <math.h>

#define NB 128
#define NJ 32
#define NI 1152
#define NN 16
#define TI 32
#define NTILES 36

// ---------- global scratch ----------
__device__ float    g_V0[NB * NJ * NN];
__device__ float    g_V1[NB * NJ * NN];
__device__ float    g_VW[NB * NJ * NN];                // v0 + v1
__device__ float    g_S_part[NTILES * NB * NJ * NN];
__device__ float    g_sc_part[NTILES * NB * NJ];
__device__ float    g_ent_part[2 * NTILES * NB];
__device__ unsigned g_mask1[NB];
__device__ unsigned g_mask2[NB];

// =====================================================================
// Pass 1: s0 = (1/32)*sum_i u ; v0 = squash(s0 + bias)
// =====================================================================
__global__ void __launch_bounds__(256) pass1_kernel(const float* __restrict__ u,
                                                    const float* __restrict__ bias) {
    __shared__ float sred[64 * 17];
    int j = blockIdx.x, b = blockIdx.y;
    int t = threadIdx.x;
    int q = t & 3, ir = t >> 2;
    const float* base = u + (size_t)(b * NJ + j) * (NI * NN);
    float4 acc = make_float4(0.f, 0.f, 0.f, 0.f);
#pragma unroll
    for (int k = 0; k < 18; ++k) {
        int i = ir + k * 64;
        float4 v = *reinterpret_cast<const float4*>(base + (size_t)i * NN + q * 4);
        acc.x += v.x; acc.y += v.y; acc.z += v.z; acc.w += v.w;
    }
    float* sp = sred + ir * 17 + q * 4;
    sp[0] = acc.x; sp[1] = acc.y; sp[2] = acc.z; sp[3] = acc.w;
    __syncthreads();
    if (t < 16) {
        int n = t;
        float s = 0.f;
        for (int r = 0; r < 64; ++r) s += sred[r * 17 + n];
        s *= (1.f / 32.f);
        float ss = s;
#pragma unroll
        for (int o = 8; o; o >>= 1) ss += __shfl_xor_sync(0xFFFFu, ss, o);
        float tb = (ss == 0.f) ? 0.f : (s + bias[j * NN + n]);
        float sq = tb * tb;
#pragma unroll
        for (int o = 8; o; o >>= 1) sq += __shfl_xor_sync(0xFFFFu, sq, o);
        float v = (sq / (1.f + sq)) * tb / sqrtf(sq + 1e-8f);
        g_V0[(b * NJ + j) * NN + n] = v;
    }
}

// =====================================================================
// Barrier-free streaming sweep. Warp owns 4 i-rows end-to-end:
// lane (s = lane>>2, q = lane&3) covers j-slot (it*8+s), n-quad q.
// Per row: predicated loads -> quad-butterfly dot -> xor shuffle
// softmax (+entropy / +score) -> register-held weighted accumulate.
// No __syncthreads in the stream; 1-2 at the tail for warp reduction.
// =====================================================================
template <int KSEL, bool IS_SUM>
__global__ void __launch_bounds__(256, 4) route_kernel(const float* __restrict__ u,
                                                       const float* __restrict__ vglob,
                                                       const unsigned* __restrict__ maskp,
                                                       int ent_slot) {
    constexpr int ITER = (KSEL + 7) / 8;
    constexpr int SWORDS = IS_SUM ? (KSEL * 16) : 32;
    __shared__ int   sj[32];
    __shared__ float red[8];
    __shared__ float ssum[8][SWORDS];

    int t = threadIdx.x, lane = t & 31, w = t >> 5;
    int tb = blockIdx.x, b = blockIdx.y, i0 = tb * TI;
    int q = lane & 3, s = lane >> 2;
    unsigned msk = maskp ? maskp[b] : 0xFFFFFFFFu;
    if (t < 32 && ((msk >> t) & 1u))
        sj[__popc(msk & ((1u << t) - 1u))] = t;
    __syncthreads();

    const float* ub = u + (size_t)b * (NJ * NI * NN);
    bool  val[ITER];
    int   off[ITER];
    float4 vj[ITER];
#pragma unroll
    for (int it = 0; it < ITER; ++it) {
        int idx = it * 8 + s;
        val[it] = (idx < KSEL);
        int j = sj[val[it] ? idx : 0];
        off[it] = j * (NI * NN) + q * 4;
        vj[it] = *reinterpret_cast<const float4*>(vglob + (b * NJ + j) * NN + q * 4);
    }

    float4 acc[IS_SUM ? ITER : 1];
    float  sc[IS_SUM ? 1 : ITER];
#pragma unroll
    for (int it = 0; it < (IS_SUM ? ITER : 1); ++it) acc[it] = make_float4(0.f, 0.f, 0.f, 0.f);
#pragma unroll
    for (int it = 0; it < (IS_SUM ? 1 : ITER); ++it) sc[it] = 0.f;
    float ent = 0.f;

#pragma unroll 2
    for (int r = 0; r < 4; ++r) {
        int i = i0 + w * 4 + r;
        float4 uu[ITER];
        float  d[ITER];
#pragma unroll
        for (int it = 0; it < ITER; ++it) {
            uu[it] = make_float4(0.f, 0.f, 0.f, 0.f);
            if (val[it])
                uu[it] = *reinterpret_cast<const float4*>(ub + off[it] + i * NN);
        }
#pragma unroll
        for (int it = 0; it < ITER; ++it) {
            float dd = uu[it].x * vj[it].x + uu[it].y * vj[it].y
                     + uu[it].z * vj[it].z + uu[it].w * vj[it].w;
            dd += __shfl_xor_sync(0xFFFFFFFFu, dd, 1);
            dd += __shfl_xor_sync(0xFFFFFFFFu, dd, 2);
            d[it] = val[it] ? dd : -INFINITY;
        }
        // row max over all j-slots
        float mx = d[0];
#pragma unroll
        for (int it = 1; it < ITER; ++it) mx = fmaxf(mx, d[it]);
        mx = fmaxf(mx, __shfl_xor_sync(0xFFFFFFFFu, mx, 4));
        mx = fmaxf(mx, __shfl_xor_sync(0xFFFFFFFFu, mx, 8));
        mx = fmaxf(mx, __shfl_xor_sync(0xFFFFFFFFu, mx, 16));
        // exp, denominator (and c·d for entropy) — CD guarded against 0*inf
        float e[ITER];
        float S = 0.f, CD = 0.f;
#pragma unroll
        for (int it = 0; it < ITER; ++it) {
            e[it] = val[it] ? expf(d[it] - mx) : 0.f;
            S += e[it];
            if (IS_SUM && val[it]) CD += e[it] * d[it];
        }
        S += __shfl_xor_sync(0xFFFFFFFFu, S, 4);
        S += __shfl_xor_sync(0xFFFFFFFFu, S, 8);
        S += __shfl_xor_sync(0xFFFFFFFFu, S, 16);
        if (IS_SUM) {
            CD += __shfl_xor_sync(0xFFFFFFFFu, CD, 4);
            CD += __shfl_xor_sync(0xFFFFFFFFu, CD, 8);
            CD += __shfl_xor_sync(0xFFFFFFFFu, CD, 16);
        }
        float inv = 1.f / S;
        if (IS_SUM) {
            ent += mx + logf(S) - CD * inv;
#pragma unroll
            for (int it = 0; it < ITER; ++it) {
                float c = e[it] * inv;
                acc[it].x += c * uu[it].x;
                acc[it].y += c * uu[it].y;
                acc[it].z += c * uu[it].z;
                acc[it].w += c * uu[it].w;
            }
        } else {
#pragma unroll
            for (int it = 0; it < ITER; ++it) sc[it] += e[it] * inv;
        }
    }

    if (!IS_SUM) {
        // per-warp scores -> smem -> per-tile partials (all 32 j, zeros for unselected)
        if (q == 0) {
#pragma unroll
            for (int it = 0; it < ITER; ++it)
                if (val[it]) ssum[w][it * 8 + s] = sc[it];
        }
        __syncthreads();
        if (t < 32) {
            bool selj = (msk >> t) & 1u;
            float v = 0.f;
            if (selj) {
                int idx = __popc(msk & ((1u << t) - 1u));
#pragma unroll
                for (int ww = 0; ww < 8; ++ww) v += ssum[ww][idx];
            }
            g_sc_part[tb * (NB * NJ) + b * NJ + t] = v;
        }
    } else {
        // per-warp s partials -> smem -> per-tile partials
#pragma unroll
        for (int it = 0; it < ITER; ++it) {
            if (val[it]) {
                int base = (it * 8 + s) * 16 + q * 4;
                *reinterpret_cast<float4*>(&ssum[w][base]) = acc[it];
            }
        }
        if (lane == 0) red[w] = ent;
        __syncthreads();
        for (int k = t; k < KSEL * 16; k += 256) {
            float v = 0.f;
#pragma unroll
            for (int ww = 0; ww < 8; ++ww) v += ssum[ww][k];
            int idx = k >> 4, n = k & 15;
            int j = sj[idx];
            g_S_part[(size_t)tb * (NB * NJ * NN) + (size_t)(b * NJ + j) * NN + n] = v;
        }
        if (t == 0) {
            float e = 0.f;
#pragma unroll
            for (int x = 0; x < 8; ++x) e += red[x];
            g_ent_part[ent_slot * (NTILES * NB) + tb * NB + b] = e;
        }
    }
}

// =====================================================================
// top-k per example (tie-break: lower index wins)
// =====================================================================
__global__ void topk_kernel(int K, int which) {
    int b = blockIdx.x, j = threadIdx.x;
    float sc = 0.f;
#pragma unroll 6
    for (int tt = 0; tt < NTILES; ++tt) sc += g_sc_part[tt * (NB * NJ) + b * NJ + j];
    int rank = 0;
#pragma unroll
    for (int k = 0; k < 32; ++k) {
        float o = __shfl_sync(0xFFFFFFFFu, sc, k);
        rank += (o > sc) || (o == sc && k < j);
    }
    unsigned m = __ballot_sync(0xFFFFFFFFu, rank < K);
    if (j == 0) {
        if (which == 1) g_mask1[b] = m; else g_mask2[b] = m;
    }
}

// =====================================================================
// squash from s partials (mask-aware; unselected capsules -> v = 0)
// =====================================================================
__device__ __forceinline__ float squash_elem(int gid, bool sel, const float* __restrict__ bias) {
    float s = 0.f;
    if (sel) {
#pragma unroll 6
        for (int tt = 0; tt < NTILES; ++tt) s += g_S_part[(size_t)tt * (NB * NJ * NN) + gid];
    }
    float ss = s;
#pragma unroll
    for (int o = 8; o; o >>= 1) ss += __shfl_xor_sync(0xFFFFFFFFu, ss, o);
    int n = gid & 15, j = (gid >> 4) & 31;
    float tb = (ss == 0.f) ? 0.f : (s + bias[j * NN + n]);
    float sq = tb * tb;
#pragma unroll
    for (int o = 8; o; o >>= 1) sq += __shfl_xor_sync(0xFFFFFFFFu, sq, o);
    return (sq == 0.f) ? 0.f : (sq / (1.f + sq)) * tb / sqrtf(sq + 1e-8f);
}

__global__ void __launch_bounds__(256) squash_mid_kernel(const float* __restrict__ bias) {
    int gid = blockIdx.x * 256 + threadIdx.x;
    int j = (gid >> 4) & 31, b = gid >> 9;
    bool sel = (g_mask1[b] >> j) & 1u;
    float v = squash_elem(gid, sel, bias);
    g_V1[gid] = v;
    g_VW[gid] = g_V0[gid] + v;
}

__global__ void __launch_bounds__(256) final_kernel(const float* __restrict__ bias,
                                                    float* __restrict__ out, int out_size) {
    int gid = blockIdx.x * 256 + threadIdx.x;
    int j = (gid >> 4) & 31, b = gid >> 9;
    bool sel = (g_mask2[b] >> j) & 1u;
    out[gid] = squash_elem(gid, sel, bias);
    if (blockIdx.x == 0 && threadIdx.x < NB && out_size >= NB * NJ * NN + NB * 3) {
        int bb = threadIdx.x;
        float e1 = 0.f, e2 = 0.f;
        for (int tt = 0; tt < NTILES; ++tt) {
            e1 += g_ent_part[0 * (NTILES * NB) + tt * NB + bb];
            e2 += g_ent_part[1 * (NTILES * NB) + tt * NB + bb];
        }
        float* eo = out + NB * NJ * NN;
        eo[bb * 3 + 0] = logf(32.0f);
        eo[bb * 3 + 1] = e1 * (1.f / (float)NI);
        eo[bb * 3 + 2] = e2 * (1.f / (float)NI);
    }
}

// =====================================================================
extern "C" void kernel_launch(void* const* d_in, const int* in_sizes, int n_in,
                              void* d_out, int out_size) {
    const float* u    = (const float*)d_in[0];
    const float* bias = (const float*)d_in[1];
    float* out        = (float*)d_out;

    float *v0p, *vwp;
    unsigned *m1p, *m2p;
    cudaGetSymbolAddress((void**)&v0p, g_V0);
    cudaGetSymbolAddress((void**)&vwp, g_VW);
    cudaGetSymbolAddress((void**)&m1p, g_mask1);
    cudaGetSymbolAddress((void**)&m2p, g_mask2);

    dim3 sgrid(NTILES, NB);

    // sweep 1 (302 MB): s0 -> v0
    pass1_kernel<<<dim3(NJ, NB), 256>>>(u, bias);
    // sweep 2 (302 MB): scores of softmax(u·v0) -> top-20 -> mask1
    route_kernel<32, false><<<sgrid, 256>>>(u, v0p, nullptr, 0);
    topk_kernel<<<NB, 32>>>(20, 1);
    // sweep 3 (189 MB): c1, entropy1, s1 -> v1, w = v0 + v1
    route_kernel<20, true><<<sgrid, 256>>>(u, v0p, m1p, 0);
    squash_mid_kernel<<<256, 256>>>(bias);
    // sweep 4 (189 MB): scores of softmax(u·w, mask1) -> top-12 -> mask2
    route_kernel<20, false><<<sgrid, 256>>>(u, vwp, m1p, 0);
    topk_kernel<<<NB, 32>>>(12, 2);
    // sweep 5 (113 MB): c2, entropy2, s2 -> v2 (out)
    route_kernel<12, true><<<sgrid, 256>>>(u, vwp, m2p, 1);
    final_kernel<<<256, 256>>>(bias, out, out_size);
}

// round 8
// speedup vs baseline: 1.2288x; 1.0474x over previous
#include <cuda_runtime.h>
#include <math.h>

#define NB 128
#define NJ 32
#define NI 1152
#define NN 16
#define TI 32
#define NTILES 36

// ---------- global scratch ----------
__device__ float    g_V0[NB * NJ * NN];
__device__ float    g_V1[NB * NJ * NN];
__device__ float    g_VW[NB * NJ * NN];                // v0 + v1
__device__ float    g_S_part[NTILES * NB * NJ * NN];
__device__ float    g_sc_part[NTILES * NB * NJ];
__device__ float    g_ent_part[2 * NTILES * NB];
__device__ unsigned g_mask1[NB];
__device__ unsigned g_mask2[NB];

// =====================================================================
// Pass 1: s0 = (1/32)*sum_i u ; v0 = squash(s0 + bias)
// =====================================================================
__global__ void __launch_bounds__(256) pass1_kernel(const float* __restrict__ u,
                                                    const float* __restrict__ bias) {
    __shared__ float sred[64 * 17];
    int j = blockIdx.x, b = blockIdx.y;
    int t = threadIdx.x;
    int q = t & 3, ir = t >> 2;
    const float* base = u + (size_t)(b * NJ + j) * (NI * NN);
    float4 acc = make_float4(0.f, 0.f, 0.f, 0.f);
#pragma unroll
    for (int k = 0; k < 18; ++k) {
        int i = ir + k * 64;
        float4 v = *reinterpret_cast<const float4*>(base + (size_t)i * NN + q * 4);
        acc.x += v.x; acc.y += v.y; acc.z += v.z; acc.w += v.w;
    }
    float* sp = sred + ir * 17 + q * 4;
    sp[0] = acc.x; sp[1] = acc.y; sp[2] = acc.z; sp[3] = acc.w;
    __syncthreads();
    if (t < 16) {
        int n = t;
        float s = 0.f;
        for (int r = 0; r < 64; ++r) s += sred[r * 17 + n];
        s *= (1.f / 32.f);
        float ss = s;
#pragma unroll
        for (int o = 8; o; o >>= 1) ss += __shfl_xor_sync(0xFFFFu, ss, o);
        float tb = (ss == 0.f) ? 0.f : (s + bias[j * NN + n]);
        float sq = tb * tb;
#pragma unroll
        for (int o = 8; o; o >>= 1) sq += __shfl_xor_sync(0xFFFFu, sq, o);
        float v = (sq / (1.f + sq)) * tb / sqrtf(sq + 1e-8f);
        g_V0[(b * NJ + j) * NN + n] = v;
    }
}

// =====================================================================
// Barrier-free streaming sweep, shift-free softmax, 2-deep row pipeline.
// Warp owns 4 i-rows; lane (s=lane>>2, q=lane&3) covers j-slot it*8+s,
// n-quad q. No __syncthreads in the stream.
// =====================================================================
template <int KSEL, bool IS_SUM>
__global__ void __launch_bounds__(256, 4) route_kernel(const float* __restrict__ u,
                                                       const float* __restrict__ vglob,
                                                       const unsigned* __restrict__ maskp,
                                                       int ent_slot) {
    constexpr int ITER = (KSEL + 7) / 8;
    constexpr int SWORDS = IS_SUM ? (KSEL * 16) : 32;
    __shared__ int   sj[32];
    __shared__ float red[8];
    __shared__ float ssum[8][SWORDS];

    int t = threadIdx.x, lane = t & 31, w = t >> 5;
    int tb = blockIdx.x, b = blockIdx.y, i0 = tb * TI;
    int q = lane & 3, s = lane >> 2;
    unsigned msk = maskp ? maskp[b] : 0xFFFFFFFFu;
    if (t < 32 && ((msk >> t) & 1u))
        sj[__popc(msk & ((1u << t) - 1u))] = t;
    __syncthreads();

    const float* ub = u + (size_t)b * (NJ * NI * NN);
    bool  val[ITER];
    int   off[ITER];
    float4 vj[ITER];
#pragma unroll
    for (int it = 0; it < ITER; ++it) {
        int idx = it * 8 + s;
        val[it] = (idx < KSEL);
        int j = sj[val[it] ? idx : 0];
        off[it] = j * (NI * NN) + q * 4;
        vj[it] = *reinterpret_cast<const float4*>(vglob + (b * NJ + j) * NN + q * 4);
    }

    float4 acc[IS_SUM ? ITER : 1];
    float  sc[IS_SUM ? 1 : ITER];
#pragma unroll
    for (int it = 0; it < (IS_SUM ? ITER : 1); ++it) acc[it] = make_float4(0.f, 0.f, 0.f, 0.f);
#pragma unroll
    for (int it = 0; it < (IS_SUM ? 1 : ITER); ++it) sc[it] = 0.f;
    float ent = 0.f;

    // preload row 0
    float4 un[ITER];
    {
        int i = i0 + w * 4;
#pragma unroll
        for (int it = 0; it < ITER; ++it) {
            un[it] = make_float4(0.f, 0.f, 0.f, 0.f);
            if (val[it])
                un[it] = *reinterpret_cast<const float4*>(ub + off[it] + i * NN);
        }
    }

#pragma unroll
    for (int r = 0; r < 4; ++r) {
        float4 uu[ITER];
#pragma unroll
        for (int it = 0; it < ITER; ++it) uu[it] = un[it];
        // issue next row's loads before this row's math
        if (r < 3) {
            int i = i0 + w * 4 + r + 1;
#pragma unroll
            for (int it = 0; it < ITER; ++it) {
                un[it] = make_float4(0.f, 0.f, 0.f, 0.f);
                if (val[it])
                    un[it] = *reinterpret_cast<const float4*>(ub + off[it] + i * NN);
            }
        }
        // shift-free softmax: e = exp(d), S = sum e, c = e/S
        float e[ITER], d[ITER];
        float S = 0.f, CD = 0.f;
#pragma unroll
        for (int it = 0; it < ITER; ++it) {
            float dd = uu[it].x * vj[it].x + uu[it].y * vj[it].y
                     + uu[it].z * vj[it].z + uu[it].w * vj[it].w;
            dd += __shfl_xor_sync(0xFFFFFFFFu, dd, 1);
            dd += __shfl_xor_sync(0xFFFFFFFFu, dd, 2);
            d[it] = dd;
            e[it] = val[it] ? __expf(dd) : 0.f;
            S += e[it];
            if (IS_SUM && val[it]) CD += e[it] * dd;
        }
        S += __shfl_xor_sync(0xFFFFFFFFu, S, 4);
        S += __shfl_xor_sync(0xFFFFFFFFu, S, 8);
        S += __shfl_xor_sync(0xFFFFFFFFu, S, 16);
        if (IS_SUM) {
            CD += __shfl_xor_sync(0xFFFFFFFFu, CD, 4);
            CD += __shfl_xor_sync(0xFFFFFFFFu, CD, 8);
            CD += __shfl_xor_sync(0xFFFFFFFFu, CD, 16);
        }
        float inv = 1.f / S;
        if (IS_SUM) {
            ent += __logf(S) - CD * inv;
#pragma unroll
            for (int it = 0; it < ITER; ++it) {
                float c = e[it] * inv;
                acc[it].x += c * uu[it].x;
                acc[it].y += c * uu[it].y;
                acc[it].z += c * uu[it].z;
                acc[it].w += c * uu[it].w;
            }
        } else {
#pragma unroll
            for (int it = 0; it < ITER; ++it) sc[it] += e[it] * inv;
        }
    }

    if (!IS_SUM) {
        // per-warp scores -> smem -> per-tile partials
        if (q == 0) {
#pragma unroll
            for (int it = 0; it < ITER; ++it)
                if (val[it]) ssum[w][it * 8 + s] = sc[it];
        }
        __syncthreads();
        if (t < 32) {
            bool selj = (msk >> t) & 1u;
            float v = 0.f;
            if (selj) {
                int idx = __popc(msk & ((1u << t) - 1u));
#pragma unroll
                for (int ww = 0; ww < 8; ++ww) v += ssum[ww][idx];
            }
            g_sc_part[tb * (NB * NJ) + b * NJ + t] = v;
        }
    } else {
        // per-warp s partials -> smem -> per-tile partials
#pragma unroll
        for (int it = 0; it < ITER; ++it) {
            if (val[it]) {
                int base = (it * 8 + s) * 16 + q * 4;
                *reinterpret_cast<float4*>(&ssum[w][base]) = acc[it];
            }
        }
        if (lane == 0) red[w] = ent;
        __syncthreads();
        for (int k = t; k < KSEL * 16; k += 256) {
            float v = 0.f;
#pragma unroll
            for (int ww = 0; ww < 8; ++ww) v += ssum[ww][k];
            int idx = k >> 4, n = k & 15;
            int j = sj[idx];
            g_S_part[(size_t)tb * (NB * NJ * NN) + (size_t)(b * NJ + j) * NN + n] = v;
        }
        if (t == 0) {
            float e = 0.f;
#pragma unroll
            for (int x = 0; x < 8; ++x) e += red[x];
            g_ent_part[ent_slot * (NTILES * NB) + tb * NB + b] = e;
        }
    }
}

// =====================================================================
// top-k per example (tie-break: lower index wins)
// =====================================================================
__global__ void topk_kernel(int K, int which) {
    int b = blockIdx.x, j = threadIdx.x;
    float sc = 0.f;
#pragma unroll 6
    for (int tt = 0; tt < NTILES; ++tt) sc += g_sc_part[tt * (NB * NJ) + b * NJ + j];
    int rank = 0;
#pragma unroll
    for (int k = 0; k < 32; ++k) {
        float o = __shfl_sync(0xFFFFFFFFu, sc, k);
        rank += (o > sc) || (o == sc && k < j);
    }
    unsigned m = __ballot_sync(0xFFFFFFFFu, rank < K);
    if (j == 0) {
        if (which == 1) g_mask1[b] = m; else g_mask2[b] = m;
    }
}

// =====================================================================
// squash from s partials (mask-aware; unselected capsules -> v = 0)
// =====================================================================
__device__ __forceinline__ float squash_elem(int gid, bool sel, const float* __restrict__ bias) {
    float s = 0.f;
    if (sel) {
#pragma unroll 6
        for (int tt = 0; tt < NTILES; ++tt) s += g_S_part[(size_t)tt * (NB * NJ * NN) + gid];
    }
    float ss = s;
#pragma unroll
    for (int o = 8; o; o >>= 1) ss += __shfl_xor_sync(0xFFFFFFFFu, ss, o);
    int n = gid & 15, j = (gid >> 4) & 31;
    float tb = (ss == 0.f) ? 0.f : (s + bias[j * NN + n]);
    float sq = tb * tb;
#pragma unroll
    for (int o = 8; o; o >>= 1) sq += __shfl_xor_sync(0xFFFFFFFFu, sq, o);
    return (sq == 0.f) ? 0.f : (sq / (1.f + sq)) * tb / sqrtf(sq + 1e-8f);
}

__global__ void __launch_bounds__(256) squash_mid_kernel(const float* __restrict__ bias) {
    int gid = blockIdx.x * 256 + threadIdx.x;
    int j = (gid >> 4) & 31, b = gid >> 9;
    bool sel = (g_mask1[b] >> j) & 1u;
    float v = squash_elem(gid, sel, bias);
    g_V1[gid] = v;
    g_VW[gid] = g_V0[gid] + v;
}

__global__ void __launch_bounds__(256) final_kernel(const float* __restrict__ bias,
                                                    float* __restrict__ out, int out_size) {
    int gid = blockIdx.x * 256 + threadIdx.x;
    int j = (gid >> 4) & 31, b = gid >> 9;
    bool sel = (g_mask2[b] >> j) & 1u;
    out[gid] = squash_elem(gid, sel, bias);
    if (blockIdx.x == 0 && threadIdx.x < NB && out_size >= NB * NJ * NN + NB * 3) {
        int bb = threadIdx.x;
        float e1 = 0.f, e2 = 0.f;
        for (int tt = 0; tt < NTILES; ++tt) {
            e1 += g_ent_part[0 * (NTILES * NB) + tt * NB + bb];
            e2 += g_ent_part[1 * (NTILES * NB) + tt * NB + bb];
        }
        float* eo = out + NB * NJ * NN;
        eo[bb * 3 + 0] = logf(32.0f);
        eo[bb * 3 + 1] = e1 * (1.f / (float)NI);
        eo[bb * 3 + 2] = e2 * (1.f / (float)NI);
    }
}

// =====================================================================
extern "C" void kernel_launch(void* const* d_in, const int* in_sizes, int n_in,
                              void* d_out, int out_size) {
    const float* u    = (const float*)d_in[0];
    const float* bias = (const float*)d_in[1];
    float* out        = (float*)d_out;

    float *v0p, *vwp;
    unsigned *m1p, *m2p;
    cudaGetSymbolAddress((void**)&v0p, g_V0);
    cudaGetSymbolAddress((void**)&vwp, g_VW);
    cudaGetSymbolAddress((void**)&m1p, g_mask1);
    cudaGetSymbolAddress((void**)&m2p, g_mask2);

    dim3 sgrid(NTILES, NB);

    // sweep 1 (302 MB): s0 -> v0
    pass1_kernel<<<dim3(NJ, NB), 256>>>(u, bias);
    // sweep 2 (302 MB): scores of softmax(u·v0) -> top-20 -> mask1
    route_kernel<32, false><<<sgrid, 256>>>(u, v0p, nullptr, 0);
    topk_kernel<<<NB, 32>>>(20, 1);
    // sweep 3 (189 MB): c1, entropy1, s1 -> v1, w = v0 + v1
    route_kernel<20, true><<<sgrid, 256>>>(u, v0p, m1p, 0);
    squash_mid_kernel<<<256, 256>>>(bias);
    // sweep 4 (189 MB): scores of softmax(u·w, mask1) -> top-12 -> mask2
    route_kernel<20, false><<<sgrid, 256>>>(u, vwp, m1p, 0);
    topk_kernel<<<NB, 32>>>(12, 2);
    // sweep 5 (113 MB): c2, entropy2, s2 -> v2 (out)
    route_kernel<12, true><<<sgrid, 256>>>(u, vwp, m2p, 1);
    final_kernel<<<256, 256>>>(bias, out, out_size);
}

// round 9
// speedup vs baseline: 1.3333x; 1.0851x over previous
#include <cuda_runtime.h>
#include <math.h>

#define NB 128
#define NJ 32
#define NI 1152
#define NN 16
#define TI 64
#define NTILES 18

// ---------- global scratch ----------
__device__ float    g_V0[NB * NJ * NN];
__device__ float    g_V1[NB * NJ * NN];
__device__ float    g_VW[NB * NJ * NN];                // v0 + v1
__device__ float    g_S_part[NTILES * NB * NJ * NN];
__device__ float    g_sc_part[NTILES * NB * NJ];
__device__ float    g_ent_part[2 * NTILES * NB];
__device__ unsigned g_mask1[NB];
__device__ unsigned g_mask2[NB];

// =====================================================================
// Pass 1: s0 = (1/32)*sum_i u ; v0 = squash(s0 + bias)
// =====================================================================
__global__ void __launch_bounds__(256) pass1_kernel(const float* __restrict__ u,
                                                    const float* __restrict__ bias) {
    __shared__ float sred[64 * 17];
    int j = blockIdx.x, b = blockIdx.y;
    int t = threadIdx.x;
    int q = t & 3, ir = t >> 2;
    const float* base = u + (size_t)(b * NJ + j) * (NI * NN);
    float4 acc = make_float4(0.f, 0.f, 0.f, 0.f);
#pragma unroll
    for (int k = 0; k < 18; ++k) {
        int i = ir + k * 64;
        float4 v = *reinterpret_cast<const float4*>(base + (size_t)i * NN + q * 4);
        acc.x += v.x; acc.y += v.y; acc.z += v.z; acc.w += v.w;
    }
    float* sp = sred + ir * 17 + q * 4;
    sp[0] = acc.x; sp[1] = acc.y; sp[2] = acc.z; sp[3] = acc.w;
    __syncthreads();
    if (t < 16) {
        int n = t;
        float s = 0.f;
        for (int r = 0; r < 64; ++r) s += sred[r * 17 + n];
        s *= (1.f / 32.f);
        float ss = s;
#pragma unroll
        for (int o = 8; o; o >>= 1) ss += __shfl_xor_sync(0xFFFFu, ss, o);
        float tb = (ss == 0.f) ? 0.f : (s + bias[j * NN + n]);
        float sq = tb * tb;
#pragma unroll
        for (int o = 8; o; o >>= 1) sq += __shfl_xor_sync(0xFFFFu, sq, o);
        float v = (sq / (1.f + sq)) * tb / sqrtf(sq + 1e-8f);
        g_V0[(b * NJ + j) * NN + n] = v;
    }
}

// =====================================================================
// Barrier-free streaming sweep, shift-free softmax, 2-deep row pipeline,
// deferred entropy reduction. Warp owns 8 i-rows; lane (s=lane>>2,
// q=lane&3) covers j-slot it*8+s, n-quad q.
// =====================================================================
template <int KSEL, bool IS_SUM>
__global__ void __launch_bounds__(256, 4) route_kernel(const float* __restrict__ u,
                                                       const float* __restrict__ vglob,
                                                       const unsigned* __restrict__ maskp,
                                                       int ent_slot) {
    constexpr int ITER = (KSEL + 7) / 8;
    constexpr int SWORDS = IS_SUM ? (KSEL * 16) : 32;
    __shared__ int   sj[32];
    __shared__ float red[8];
    __shared__ float ssum[8][SWORDS];

    int t = threadIdx.x, lane = t & 31, w = t >> 5;
    int tb = blockIdx.x, b = blockIdx.y, i0 = tb * TI;
    int q = lane & 3, s = lane >> 2;
    unsigned msk = maskp ? maskp[b] : 0xFFFFFFFFu;
    if (t < 32 && ((msk >> t) & 1u))
        sj[__popc(msk & ((1u << t) - 1u))] = t;
    __syncthreads();

    const float* ub = u + (size_t)b * (NJ * NI * NN);
    bool  val[ITER];
    int   off[ITER];
    float4 vj[ITER];
#pragma unroll
    for (int it = 0; it < ITER; ++it) {
        int idx = it * 8 + s;
        val[it] = (idx < KSEL);
        int j = sj[val[it] ? idx : 0];
        off[it] = j * (NI * NN) + q * 4;
        vj[it] = *reinterpret_cast<const float4*>(vglob + (b * NJ + j) * NN + q * 4);
    }

    float4 acc[IS_SUM ? ITER : 1];
    float  sc[IS_SUM ? 1 : ITER];
#pragma unroll
    for (int it = 0; it < (IS_SUM ? ITER : 1); ++it) acc[it] = make_float4(0.f, 0.f, 0.f, 0.f);
#pragma unroll
    for (int it = 0; it < (IS_SUM ? 1 : ITER); ++it) sc[it] = 0.f;
    float entlog = 0.f;   // sum of log S (identical across lanes)
    float cdacc  = 0.f;   // lane-local sum of (local CD)*inv, reduced at tail

    // preload row 0
    float4 un[ITER];
    {
        int i = i0 + w * 8;
#pragma unroll
        for (int it = 0; it < ITER; ++it) {
            un[it] = make_float4(0.f, 0.f, 0.f, 0.f);
            if (val[it])
                un[it] = *reinterpret_cast<const float4*>(ub + off[it] + i * NN);
        }
    }

#pragma unroll
    for (int r = 0; r < 8; ++r) {
        float4 uu[ITER];
#pragma unroll
        for (int it = 0; it < ITER; ++it) uu[it] = un[it];
        if (r < 7) {
            int i = i0 + w * 8 + r + 1;
#pragma unroll
            for (int it = 0; it < ITER; ++it) {
                un[it] = make_float4(0.f, 0.f, 0.f, 0.f);
                if (val[it])
                    un[it] = *reinterpret_cast<const float4*>(ub + off[it] + i * NN);
            }
        }
        // shift-free softmax: e = exp(d), S = sum e, c = e/S
        float e[ITER];
        float S = 0.f, CDloc = 0.f;
#pragma unroll
        for (int it = 0; it < ITER; ++it) {
            float dd = uu[it].x * vj[it].x + uu[it].y * vj[it].y
                     + uu[it].z * vj[it].z + uu[it].w * vj[it].w;
            dd += __shfl_xor_sync(0xFFFFFFFFu, dd, 1);
            dd += __shfl_xor_sync(0xFFFFFFFFu, dd, 2);
            e[it] = val[it] ? __expf(dd) : 0.f;
            S += e[it];
            if (IS_SUM && val[it]) CDloc += e[it] * dd;
        }
        S += __shfl_xor_sync(0xFFFFFFFFu, S, 4);
        S += __shfl_xor_sync(0xFFFFFFFFu, S, 8);
        S += __shfl_xor_sync(0xFFFFFFFFu, S, 16);
        float inv = 1.f / S;
        if (IS_SUM) {
            entlog += __logf(S);
            cdacc  += CDloc * inv;   // deferred cross-lane reduce
#pragma unroll
            for (int it = 0; it < ITER; ++it) {
                float c = e[it] * inv;
                acc[it].x += c * uu[it].x;
                acc[it].y += c * uu[it].y;
                acc[it].z += c * uu[it].z;
                acc[it].w += c * uu[it].w;
            }
        } else {
#pragma unroll
            for (int it = 0; it < ITER; ++it) sc[it] += e[it] * inv;
        }
    }

    if (!IS_SUM) {
        // per-warp scores -> smem -> per-tile partials
        if (q == 0) {
#pragma unroll
            for (int it = 0; it < ITER; ++it)
                if (val[it]) ssum[w][it * 8 + s] = sc[it];
        }
        __syncthreads();
        if (t < 32) {
            bool selj = (msk >> t) & 1u;
            float v = 0.f;
            if (selj) {
                int idx = __popc(msk & ((1u << t) - 1u));
#pragma unroll
                for (int ww = 0; ww < 8; ++ww) v += ssum[ww][idx];
            }
            g_sc_part[tb * (NB * NJ) + b * NJ + t] = v;
        }
    } else {
        // finish entropy: reduce cdacc across the 8 s-groups (q-lanes identical)
        cdacc += __shfl_xor_sync(0xFFFFFFFFu, cdacc, 4);
        cdacc += __shfl_xor_sync(0xFFFFFFFFu, cdacc, 8);
        cdacc += __shfl_xor_sync(0xFFFFFFFFu, cdacc, 16);
        float ent = entlog - cdacc;
        // per-warp s partials -> smem -> per-tile partials
#pragma unroll
        for (int it = 0; it < ITER; ++it) {
            if (val[it]) {
                int base = (it * 8 + s) * 16 + q * 4;
                *reinterpret_cast<float4*>(&ssum[w][base]) = acc[it];
            }
        }
        if (lane == 0) red[w] = ent;
        __syncthreads();
        for (int k = t; k < KSEL * 16; k += 256) {
            float v = 0.f;
#pragma unroll
            for (int ww = 0; ww < 8; ++ww) v += ssum[ww][k];
            int idx = k >> 4, n = k & 15;
            int j = sj[idx];
            g_S_part[(size_t)tb * (NB * NJ * NN) + (size_t)(b * NJ + j) * NN + n] = v;
        }
        if (t == 0) {
            float e = 0.f;
#pragma unroll
            for (int x = 0; x < 8; ++x) e += red[x];
            g_ent_part[ent_slot * (NTILES * NB) + tb * NB + b] = e;
        }
    }
}

// =====================================================================
// top-k per example (tie-break: lower index wins)
// =====================================================================
__global__ void topk_kernel(int K, int which) {
    int b = blockIdx.x, j = threadIdx.x;
    float sc = 0.f;
#pragma unroll
    for (int tt = 0; tt < NTILES; ++tt) sc += g_sc_part[tt * (NB * NJ) + b * NJ + j];
    int rank = 0;
#pragma unroll
    for (int k = 0; k < 32; ++k) {
        float o = __shfl_sync(0xFFFFFFFFu, sc, k);
        rank += (o > sc) || (o == sc && k < j);
    }
    unsigned m = __ballot_sync(0xFFFFFFFFu, rank < K);
    if (j == 0) {
        if (which == 1) g_mask1[b] = m; else g_mask2[b] = m;
    }
}

// =====================================================================
// squash from s partials (mask-aware; unselected capsules -> v = 0)
// =====================================================================
__device__ __forceinline__ float squash_elem(int gid, bool sel, const float* __restrict__ bias) {
    float s = 0.f;
    if (sel) {
#pragma unroll
        for (int tt = 0; tt < NTILES; ++tt) s += g_S_part[(size_t)tt * (NB * NJ * NN) + gid];
    }
    float ss = s;
#pragma unroll
    for (int o = 8; o; o >>= 1) ss += __shfl_xor_sync(0xFFFFFFFFu, ss, o);
    int n = gid & 15, j = (gid >> 4) & 31;
    float tb = (ss == 0.f) ? 0.f : (s + bias[j * NN + n]);
    float sq = tb * tb;
#pragma unroll
    for (int o = 8; o; o >>= 1) sq += __shfl_xor_sync(0xFFFFFFFFu, sq, o);
    return (sq == 0.f) ? 0.f : (sq / (1.f + sq)) * tb / sqrtf(sq + 1e-8f);
}

__global__ void __launch_bounds__(256) squash_mid_kernel(const float* __restrict__ bias) {
    int gid = blockIdx.x * 256 + threadIdx.x;
    int j = (gid >> 4) & 31, b = gid >> 9;
    bool sel = (g_mask1[b] >> j) & 1u;
    float v = squash_elem(gid, sel, bias);
    g_V1[gid] = v;
    g_VW[gid] = g_V0[gid] + v;
}

__global__ void __launch_bounds__(256) final_kernel(const float* __restrict__ bias,
                                                    float* __restrict__ out, int out_size) {
    int gid = blockIdx.x * 256 + threadIdx.x;
    int j = (gid >> 4) & 31, b = gid >> 9;
    bool sel = (g_mask2[b] >> j) & 1u;
    out[gid] = squash_elem(gid, sel, bias);
    if (blockIdx.x == 0 && threadIdx.x < NB && out_size >= NB * NJ * NN + NB * 3) {
        int bb = threadIdx.x;
        float e1 = 0.f, e2 = 0.f;
        for (int tt = 0; tt < NTILES; ++tt) {
            e1 += g_ent_part[0 * (NTILES * NB) + tt * NB + bb];
            e2 += g_ent_part[1 * (NTILES * NB) + tt * NB + bb];
        }
        float* eo = out + NB * NJ * NN;
        eo[bb * 3 + 0] = logf(32.0f);
        eo[bb * 3 + 1] = e1 * (1.f / (float)NI);
        eo[bb * 3 + 2] = e2 * (1.f / (float)NI);
    }
}

// =====================================================================
extern "C" void kernel_launch(void* const* d_in, const int* in_sizes, int n_in,
                              void* d_out, int out_size) {
    const float* u    = (const float*)d_in[0];
    const float* bias = (const float*)d_in[1];
    float* out        = (float*)d_out;

    float *v0p, *vwp;
    unsigned *m1p, *m2p;
    cudaGetSymbolAddress((void**)&v0p, g_V0);
    cudaGetSymbolAddress((void**)&vwp, g_VW);
    cudaGetSymbolAddress((void**)&m1p, g_mask1);
    cudaGetSymbolAddress((void**)&m2p, g_mask2);

    dim3 sgrid(NTILES, NB);

    // sweep 1 (302 MB): s0 -> v0
    pass1_kernel<<<dim3(NJ, NB), 256>>>(u, bias);
    // sweep 2 (302 MB): scores of softmax(u·v0) -> top-20 -> mask1
    route_kernel<32, false><<<sgrid, 256>>>(u, v0p, nullptr, 0);
    topk_kernel<<<NB, 32>>>(20, 1);
    // sweep 3 (189 MB): c1, entropy1, s1 -> v1, w = v0 + v1
    route_kernel<20, true><<<sgrid, 256>>>(u, v0p, m1p, 0);
    squash_mid_kernel<<<256, 256>>>(bias);
    // sweep 4 (189 MB): scores of softmax(u·w, mask1) -> top-12 -> mask2
    route_kernel<20, false><<<sgrid, 256>>>(u, vwp, m1p, 0);
    topk_kernel<<<NB, 32>>>(12, 2);
    // sweep 5 (113 MB): c2, entropy2, s2 -> v2 (out)
    route_kernel<12, true><<<sgrid, 256>>>(u, vwp, m2p, 1);
    final_kernel<<<256, 256>>>(bias, out, out_size);
}